// round 14
// baseline (speedup 1.0000x reference)
#include <cuda_runtime.h>
#include <cuda_fp16.h>
#include <cuda_bf16.h>

#define N_NODES  100000
#define N_EDGES  1600000
#define NFEAT    602
#define NFEATP   608     // padded to 19*32
#define HID      128
#define NCLS     41
#define H2S      48      // padded h2 row stride in halves (cols 41..47 pad)
#define NCHUNK   4
#define CHROWS   25088   // 196 tiles of 128 rows (last chunk takes the remainder)

// ---------------- device scratch (no allocations allowed) ----------------
__device__ int   g_deg_in[N_NODES];
__device__ int   g_deg_out[N_NODES];
__device__ float g_ns[N_NODES];          // deg_out^-1/2 (clipped)
__device__ float g_nd[N_NODES];          // deg_in^-1/2  (clipped)
__device__ int   g_incl[N_NODES];        // end offset of node's csr bucket
__device__ int   g_total;                // atomic base allocator for fused scan
__device__ int   g_cursor[N_NODES];
__device__ int   g_csr[N_EDGES];         // src ids grouped by dst
__device__ __align__(16) __half g_h1h [(size_t)N_NODES * HID];  // raw x@W1 (no ns), fp16
__device__ __align__(16) __half g_h1bh[(size_t)N_NODES * HID];  // relu'd layer-1 out, fp16
__device__ __align__(16) __half g_h2h [(size_t)N_NODES * H2S];  // ns*(h1b@W2), fp16
__device__ __align__(16) __half g_w1ht[128][NFEATP];            // W1^T fp16, zero-padded
__device__ __align__(16) __half g_w2ht[64][HID];                // W2^T fp16, zero-padded

// ---------------- streams/events (created before harness baseline) ----
static cudaStream_t g_s2;
static cudaEvent_t  g_ev_fork, g_ev_join, g_evc[NCHUNK], g_ev2;
namespace {
struct StreamInit {
    StreamInit() {
        cudaStreamCreateWithFlags(&g_s2, cudaStreamNonBlocking);
        cudaEventCreateWithFlags(&g_ev_fork, cudaEventDisableTiming);
        cudaEventCreateWithFlags(&g_ev_join, cudaEventDisableTiming);
        for (int i = 0; i < NCHUNK; i++)
            cudaEventCreateWithFlags(&g_evc[i], cudaEventDisableTiming);
        cudaEventCreateWithFlags(&g_ev2, cudaEventDisableTiming);
    }
};
StreamInit g_stream_init;
}

// ---------------- cp.async helpers ----------------
__device__ __forceinline__ void cp_async16(void* dst, const void* src, int ssize) {
    asm volatile("cp.async.cg.shared.global [%0], [%1], 16, %2;\n" ::
        "r"((unsigned)__cvta_generic_to_shared(dst)), "l"(src), "r"(ssize));
}
__device__ __forceinline__ void cp_commit() {
    asm volatile("cp.async.commit_group;\n" ::: "memory");
}
__device__ __forceinline__ void cp_wait_all() {
    asm volatile("cp.async.wait_group 0;\n" ::: "memory");
}

__device__ __forceinline__ unsigned packh2(float lo, float hi) {
    __half2 h = __floats2half2_rn(lo, hi);
    return *(unsigned*)&h;
}

// ---------------- degree / norm / CSR build ----------------
__global__ void k_zero_deg() {
    int i = blockIdx.x * blockDim.x + threadIdx.x;
    if (i < N_NODES) { g_deg_in[i] = 0; g_deg_out[i] = 0; }
    if (i == 0) g_total = 0;
}

__global__ void k_count(const int* __restrict__ src, const int* __restrict__ dst) {
    int e = blockIdx.x * blockDim.x + threadIdx.x;
    if (e < N_EDGES) {
        atomicAdd(&g_deg_out[src[e]], 1);
        atomicAdd(&g_deg_in [dst[e]], 1);
    }
}

// fused: block scan + atomic block base + cursor/norm write
__global__ void k_scan_fused() {
    __shared__ int s[1024];
    __shared__ int base_sh;
    int i = blockIdx.x * 1024 + threadIdx.x;
    int di = (i < N_NODES) ? g_deg_in[i] : 0;
    s[threadIdx.x] = di;
    __syncthreads();
    for (int off = 1; off < 1024; off <<= 1) {
        int t = (threadIdx.x >= off) ? s[threadIdx.x - off] : 0;
        __syncthreads();
        s[threadIdx.x] += t;
        __syncthreads();
    }
    if (threadIdx.x == 1023) base_sh = atomicAdd(&g_total, s[1023]);
    __syncthreads();
    if (i < N_NODES) {
        int incl = s[threadIdx.x] + base_sh;
        g_incl[i] = incl;
        g_cursor[i] = incl - di;
        int dout = g_deg_out[i];
        g_ns[i] = rsqrtf((float)(dout > 1 ? dout : 1));
        g_nd[i] = rsqrtf((float)(di   > 1 ? di   : 1));
    }
}

__global__ void k_fill(const int* __restrict__ src, const int* __restrict__ dst) {
    int e = blockIdx.x * blockDim.x + threadIdx.x;
    if (e < N_EDGES) {
        int pos = atomicAdd(&g_cursor[dst[e]], 1);
        g_csr[pos] = src[e];
    }
}

// ---------------- weight convert ----------------
__global__ void k_cvtW(const float* __restrict__ W1, const float* __restrict__ W2) {
    int i = blockIdx.x * blockDim.x + threadIdx.x;
    int tot1 = 128 * NFEATP;
    if (i < tot1) {
        int n = i / NFEATP, k = i % NFEATP;
        float v = (k < NFEAT) ? W1[(long)k * HID + n] : 0.f;
        g_w1ht[n][k] = __float2half_rn(v);
    } else {
        int j = i - tot1;
        if (j < 64 * HID) {
            int n = j / HID, k = j % HID;
            float v = (n < NCLS) ? W2[(long)k * NCLS + n] : 0.f;
            g_w2ht[n][k] = __float2half_rn(v);
        }
    }
}

// ---------------- GEMM1 fp16 HMMA: h1h = fp16(x @ W1)  (raw; ns applied later) -------
#define G1_AS_BYTES (2 * 128 * 40 * 2)
#define G1_BS_BYTES (2 * 128 * 40 * 2)
#define G1_SMEM     (G1_AS_BYTES + G1_BS_BYTES)

__global__ __launch_bounds__(256, 2)
void k_gemm1_f16(const float* __restrict__ A, __half* __restrict__ out, int M) {
    extern __shared__ char smem_raw[];
    __half (*As)[128][40] = (__half(*)[128][40])smem_raw;
    __half (*Bs)[128][40] = (__half(*)[128][40])(smem_raw + G1_AS_BYTES);

    const int tid  = threadIdx.x;
    const int lane = tid & 31;
    const int w    = tid >> 5;
    const int wm   = w >> 1;
    const int wn   = w & 1;
    const int g    = lane >> 2;
    const int tig  = lane & 3;
    const int rowbase = blockIdx.y * 128;

    float acc[2][8][4];
#pragma unroll
    for (int mi = 0; mi < 2; mi++)
#pragma unroll
        for (int ni = 0; ni < 8; ni++)
#pragma unroll
            for (int j = 0; j < 4; j++) acc[mi][ni][j] = 0.f;

    float4 aReg[4];
    const int am = tid >> 3;
    const int ac = tid & 7;

    auto loadA = [&](int k0) {
#pragma unroll
        for (int i = 0; i < 4; i++) {
            int m = am + i * 32;
            int gm = rowbase + m;
            int k = k0 + ac * 4;
            float4 v = make_float4(0.f, 0.f, 0.f, 0.f);
            if (gm < M) {
                const float* p = A + (long)gm * NFEAT + k;
                if (k + 3 < NFEAT) {
                    float2 lo = *(const float2*)p;
                    float2 hi = *(const float2*)(p + 2);
                    v.x = lo.x; v.y = lo.y; v.z = hi.x; v.w = hi.y;
                } else if (k + 1 < NFEAT) {
                    float2 lo = *(const float2*)p;
                    v.x = lo.x; v.y = lo.y;
                }
            }
            aReg[i] = v;
        }
    };
    auto stsA = [&](int b) {
#pragma unroll
        for (int i = 0; i < 4; i++) {
            int m = am + i * 32;
            uint2 u;
            u.x = packh2(aReg[i].x, aReg[i].y);
            u.y = packh2(aReg[i].z, aReg[i].w);
            *(uint2*)&As[b][m][ac * 4] = u;
        }
    };
    auto issueB = [&](int k0, int b) {
#pragma unroll
        for (int i = 0; i < 2; i++) {
            int idx = tid + i * 256;
            int n = idx >> 2, c = idx & 3;
            cp_async16(&Bs[b][n][c * 8], &g_w1ht[n][k0 + c * 8], 16);
        }
    };

    const int NIT = NFEATP / 32;   // 19

    loadA(0);
    issueB(0, 0); cp_commit();
    stsA(0);
    loadA(32);

    for (int it = 0; it < NIT; it++) {
        const int cur = it & 1;
        cp_wait_all();
        __syncthreads();
        if (it + 1 < NIT) {
            stsA(cur ^ 1);
            issueB((it + 1) * 32, cur ^ 1);
            cp_commit();
        }
        if (it + 2 < NIT) loadA((it + 2) * 32);

#pragma unroll
        for (int kk = 0; kk < 32; kk += 16) {
            unsigned afr[2][4];
#pragma unroll
            for (int mi = 0; mi < 2; mi++) {
                int mb = wm * 32 + mi * 16;
                afr[mi][0] = *(const unsigned*)&As[cur][mb + g    ][kk + tig * 2];
                afr[mi][1] = *(const unsigned*)&As[cur][mb + g + 8][kk + tig * 2];
                afr[mi][2] = *(const unsigned*)&As[cur][mb + g    ][kk + tig * 2 + 8];
                afr[mi][3] = *(const unsigned*)&As[cur][mb + g + 8][kk + tig * 2 + 8];
            }
            unsigned bfr[8][2];
#pragma unroll
            for (int ni = 0; ni < 8; ni++) {
                int nb = wn * 64 + ni * 8 + g;
                bfr[ni][0] = *(const unsigned*)&Bs[cur][nb][kk + tig * 2];
                bfr[ni][1] = *(const unsigned*)&Bs[cur][nb][kk + tig * 2 + 8];
            }
#pragma unroll
            for (int mi = 0; mi < 2; mi++)
#pragma unroll
                for (int ni = 0; ni < 8; ni++) {
                    asm volatile(
                        "mma.sync.aligned.m16n8k16.row.col.f32.f16.f16.f32 "
                        "{%0,%1,%2,%3}, {%4,%5,%6,%7}, {%8,%9}, {%0,%1,%2,%3};"
                        : "+f"(acc[mi][ni][0]), "+f"(acc[mi][ni][1]),
                          "+f"(acc[mi][ni][2]), "+f"(acc[mi][ni][3])
                        : "r"(afr[mi][0]), "r"(afr[mi][1]),
                          "r"(afr[mi][2]), "r"(afr[mi][3]),
                          "r"(bfr[ni][0]), "r"(bfr[ni][1]));
                }
        }
    }

#pragma unroll
    for (int mi = 0; mi < 2; mi++) {
        int row0 = rowbase + wm * 32 + mi * 16 + g;
        int row1 = row0 + 8;
#pragma unroll
        for (int ni = 0; ni < 8; ni++) {
            int col = wn * 64 + ni * 8 + tig * 2;
            if (row0 < M)
                *(__half2*)(out + (long)row0 * HID + col) =
                    __floats2half2_rn(acc[mi][ni][0], acc[mi][ni][1]);
            if (row1 < M)
                *(__half2*)(out + (long)row1 * HID + col) =
                    __floats2half2_rn(acc[mi][ni][2], acc[mi][ni][3]);
        }
    }
}

// ---------------- GEMM2 fp16 HMMA (chunked): h2h = fp16( ns[row] * (h1bh @ W2) ) ------
__global__ __launch_bounds__(256, 2)
void k_gemm2_f16(const float* __restrict__ ns, __half* __restrict__ out, int M,
                 int rowoff) {
    __shared__ __half As[2][128][40];
    __shared__ __half Bs[2][64][40];

    const int tid  = threadIdx.x;
    const int lane = tid & 31;
    const int w    = tid >> 5;
    const int wm   = w >> 1;
    const int wn   = w & 1;
    const int g    = lane >> 2;
    const int tig  = lane & 3;
    const int rowbase = rowoff + blockIdx.y * 128;

    float acc[2][4][4];
#pragma unroll
    for (int mi = 0; mi < 2; mi++)
#pragma unroll
        for (int ni = 0; ni < 4; ni++)
#pragma unroll
            for (int j = 0; j < 4; j++) acc[mi][ni][j] = 0.f;

    auto issueA = [&](int k0, int b) {
#pragma unroll
        for (int i = 0; i < 2; i++) {
            int idx = tid + i * 256;
            int m = idx >> 2, c = idx & 3;
            int gm = rowbase + m;
            int valid = (gm < M);
            const __half* src = g_h1bh + (valid ? ((size_t)gm * HID + k0 + c * 8) : 0);
            cp_async16(&As[b][m][c * 8], src, valid ? 16 : 0);
        }
    };
    auto issueB = [&](int k0, int b) {
        int n = tid >> 2, c = tid & 3;
        cp_async16(&Bs[b][n][c * 8], &g_w2ht[n][k0 + c * 8], 16);
    };

    const int NIT = HID / 32;   // 4

    issueA(0, 0); issueB(0, 0); cp_commit();

    for (int it = 0; it < NIT; it++) {
        const int cur = it & 1;
        cp_wait_all();
        __syncthreads();
        if (it + 1 < NIT) {
            issueA((it + 1) * 32, cur ^ 1);
            issueB((it + 1) * 32, cur ^ 1);
            cp_commit();
        }

#pragma unroll
        for (int kk = 0; kk < 32; kk += 16) {
            unsigned afr[2][4];
#pragma unroll
            for (int mi = 0; mi < 2; mi++) {
                int mb = wm * 32 + mi * 16;
                afr[mi][0] = *(const unsigned*)&As[cur][mb + g    ][kk + tig * 2];
                afr[mi][1] = *(const unsigned*)&As[cur][mb + g + 8][kk + tig * 2];
                afr[mi][2] = *(const unsigned*)&As[cur][mb + g    ][kk + tig * 2 + 8];
                afr[mi][3] = *(const unsigned*)&As[cur][mb + g + 8][kk + tig * 2 + 8];
            }
            unsigned bfr[4][2];
#pragma unroll
            for (int ni = 0; ni < 4; ni++) {
                int nb = wn * 32 + ni * 8 + g;
                bfr[ni][0] = *(const unsigned*)&Bs[cur][nb][kk + tig * 2];
                bfr[ni][1] = *(const unsigned*)&Bs[cur][nb][kk + tig * 2 + 8];
            }
#pragma unroll
            for (int mi = 0; mi < 2; mi++)
#pragma unroll
                for (int ni = 0; ni < 4; ni++) {
                    asm volatile(
                        "mma.sync.aligned.m16n8k16.row.col.f32.f16.f16.f32 "
                        "{%0,%1,%2,%3}, {%4,%5,%6,%7}, {%8,%9}, {%0,%1,%2,%3};"
                        : "+f"(acc[mi][ni][0]), "+f"(acc[mi][ni][1]),
                          "+f"(acc[mi][ni][2]), "+f"(acc[mi][ni][3])
                        : "r"(afr[mi][0]), "r"(afr[mi][1]),
                          "r"(afr[mi][2]), "r"(afr[mi][3]),
                          "r"(bfr[ni][0]), "r"(bfr[ni][1]));
                }
        }
    }

#pragma unroll
    for (int mi = 0; mi < 2; mi++) {
        int row0 = rowbase + wm * 32 + mi * 16 + g;
        int row1 = row0 + 8;
        float s0 = (row0 < M) ? ns[row0] : 0.f;
        float s1 = (row1 < M) ? ns[row1] : 0.f;
#pragma unroll
        for (int ni = 0; ni < 4; ni++) {
            int col = wn * 32 + ni * 8 + tig * 2;
            if (col <= 40) {
                if (row0 < M)
                    *(__half2*)(out + (long)row0 * H2S + col) =
                        __floats2half2_rn(acc[mi][ni][0] * s0, acc[mi][ni][1] * s0);
                if (row1 < M)
                    *(__half2*)(out + (long)row1 * H2S + col) =
                        __floats2half2_rn(acc[mi][ni][2] * s1, acc[mi][ni][3] * s1);
            }
        }
    }
}

// ---------------- layer-1 aggregation (chunked): warp/node fp16 gather, ns[src] fused --
__global__ void k_agg1(const float* __restrict__ b1, int base, int count) {
    int node = base + ((blockIdx.x * blockDim.x + threadIdx.x) >> 5);
    int lane = threadIdx.x & 31;
    if (node >= base + count || node >= N_NODES) return;
    int end = g_incl[node];
    int j = end - g_deg_in[node];
    float a0 = 0.f, a1 = 0.f, a2 = 0.f, a3 = 0.f;

    auto body = [&](int s) {
        float nsv = g_ns[s];
        uint2 u = *((const uint2*)(g_h1h + (size_t)s * HID) + lane);
        float2 f0 = __half22float2(*(const __half2*)&u.x);
        float2 f1 = __half22float2(*(const __half2*)&u.y);
        a0 = fmaf(nsv, f0.x, a0);
        a1 = fmaf(nsv, f0.y, a1);
        a2 = fmaf(nsv, f1.x, a2);
        a3 = fmaf(nsv, f1.y, a3);
    };

    for (; j + 4 <= end; j += 4) {
        int s0 = g_csr[j], s1 = g_csr[j + 1], s2 = g_csr[j + 2], s3 = g_csr[j + 3];
        body(s0); body(s1); body(s2); body(s3);
    }
    for (; j < end; j++) body(g_csr[j]);

    float nd = g_nd[node];
    float4 bb = ((const float4*)b1)[lane];
    uint2 o;
    o.x = packh2(fmaxf(a0 * nd + bb.x, 0.f), fmaxf(a1 * nd + bb.y, 0.f));
    o.y = packh2(fmaxf(a2 * nd + bb.z, 0.f), fmaxf(a3 * nd + bb.w, 0.f));
    *((uint2*)(g_h1bh + (size_t)node * HID) + lane) = o;
}

// ---------------- layer-2 aggregation: warp/node fp16 gather, nd+bias ----------------
__global__ void k_agg2(const float* __restrict__ b2, float* __restrict__ out) {
    int node = (blockIdx.x * blockDim.x + threadIdx.x) >> 5;
    int lane = threadIdx.x & 31;
    if (node >= N_NODES) return;
    int end = g_incl[node];
    int j = end - g_deg_in[node];
    int c = lane * 2;
    bool act = (c < NCLS + 1);
    float a0 = 0.f, a1 = 0.f;

    auto body = [&](int s) {
        if (act) {
            float2 f = __half22float2(*(const __half2*)(g_h2h + (size_t)s * H2S + c));
            a0 += f.x; a1 += f.y;
        }
    };

    for (; j + 4 <= end; j += 4) {
        int s0 = g_csr[j], s1 = g_csr[j + 1], s2 = g_csr[j + 2], s3 = g_csr[j + 3];
        body(s0); body(s1); body(s2); body(s3);
    }
    for (; j < end; j++) body(g_csr[j]);

    if (act) {
        float nd = g_nd[node];
        float* po = out + (long)node * NCLS;
        po[c] = a0 * nd + b2[c];
        if (c + 1 < NCLS) po[c + 1] = a1 * nd + b2[c + 1];
    }
}

// ---------------- launcher ----------------
extern "C" void kernel_launch(void* const* d_in, const int* in_sizes, int n_in,
                              void* d_out, int out_size) {
    const float* x    = (const float*)d_in[0];
    const int*   esrc = (const int*)  d_in[1];
    const int*   edst = (const int*)  d_in[2];
    const float* W1   = (const float*)d_in[3];
    const float* b1   = (const float*)d_in[4];
    const float* W2   = (const float*)d_in[5];
    const float* b2   = (const float*)d_in[6];
    float*       out  = (float*)d_out;

    __half *p_h1h, *p_h2h;
    float  *p_ns;
    cudaGetSymbolAddress((void**)&p_h1h, g_h1h);
    cudaGetSymbolAddress((void**)&p_h2h, g_h2h);
    cudaGetSymbolAddress((void**)&p_ns,  g_ns);

    static bool attr_done = false;
    if (!attr_done) {
        cudaFuncSetAttribute(k_gemm1_f16,
                             cudaFuncAttributeMaxDynamicSharedMemorySize, G1_SMEM);
        attr_done = true;
    }

    const int TB = 256;

    // fork: weight-convert + GEMM1 (independent of edges) on s2; CSR chain on stream 0
    cudaEventRecord(g_ev_fork, 0);
    cudaStreamWaitEvent(g_s2, g_ev_fork, 0);
    {
        int tot = 128 * NFEATP + 64 * HID;
        k_cvtW<<<(tot + TB - 1) / TB, TB, 0, g_s2>>>(W1, W2);
        dim3 grid(1, (N_NODES + 127) / 128);
        k_gemm1_f16<<<grid, 256, G1_SMEM, g_s2>>>(x, p_h1h, N_NODES);
    }
    cudaEventRecord(g_ev_join, g_s2);

    // CSR + norms on default stream
    k_zero_deg<<<(N_NODES + TB - 1) / TB, TB>>>();
    k_count   <<<(N_EDGES + TB - 1) / TB, TB>>>(esrc, edst);
    int nb = (N_NODES + 1023) / 1024;
    k_scan_fused<<<nb, 1024>>>();
    k_fill      <<<(N_EDGES + TB - 1) / TB, TB>>>(esrc, edst);

    // join: agg1 needs h1h + csr + ns + nd
    cudaStreamWaitEvent(0, g_ev_join, 0);

    // chunked pipeline: agg1 chunk c on stream 0 -> event -> gemm2 chunk c on s2
    for (int c = 0; c < NCHUNK; c++) {
        int base  = c * CHROWS;
        int count = (c == NCHUNK - 1) ? (N_NODES - base) : CHROWS;
        k_agg1<<<(count * 32 + TB - 1) / TB, TB>>>(b1, base, count);
        cudaEventRecord(g_evc[c], 0);
        cudaStreamWaitEvent(g_s2, g_evc[c], 0);
        dim3 grid(1, (count + 127) / 128);
        k_gemm2_f16<<<grid, 256, 0, g_s2>>>(p_ns, p_h2h, N_NODES, base);
    }
    cudaEventRecord(g_ev2, g_s2);
    cudaStreamWaitEvent(0, g_ev2, 0);

    k_agg2<<<(N_NODES * 32 + TB - 1) / TB, TB>>>(b2, out);
}

// round 15
// speedup vs baseline: 1.0433x; 1.0433x over previous
#include <cuda_runtime.h>
#include <cuda_fp16.h>
#include <cuda_bf16.h>

#define N_NODES  100000
#define N_EDGES  1600000
#define NFEAT    602
#define NFEATP   608     // padded to 19*32
#define HID      128
#define NCLS     41
#define H2S      48      // padded h2 row stride in halves (cols 41..47 pad)

// ---------------- device scratch (no allocations allowed) ----------------
__device__ int   g_deg_in[N_NODES];
__device__ int   g_deg_out[N_NODES];
__device__ float g_ns[N_NODES];          // deg_out^-1/2 (clipped)
__device__ float g_nd[N_NODES];          // deg_in^-1/2  (clipped)
__device__ int   g_incl[N_NODES];        // end offset of node's csr bucket
__device__ int   g_total;                // atomic base allocator for fused scan
__device__ int   g_cursor[N_NODES];
__device__ int   g_csr[N_EDGES];         // src ids grouped by dst
__device__ __align__(16) __half g_h1h [(size_t)N_NODES * HID];  // x@W1, then *=ns (fp16)
__device__ __align__(16) __half g_h1bh[(size_t)N_NODES * HID];  // relu'd layer-1 out, fp16
__device__ __align__(16) __half g_h2h [(size_t)N_NODES * H2S];  // ns*(h1b@W2), fp16
__device__ __align__(16) __half g_w1ht[128][NFEATP];            // W1^T fp16, zero-padded
__device__ __align__(16) __half g_w2ht[64][HID];                // W2^T fp16, zero-padded

// ---------------- streams/events (created before harness baseline) ----
static cudaStream_t g_s2;
static cudaEvent_t  g_ev_fork, g_ev_join, g_ev_ns;
namespace {
struct StreamInit {
    StreamInit() {
        cudaStreamCreateWithFlags(&g_s2, cudaStreamNonBlocking);
        cudaEventCreateWithFlags(&g_ev_fork, cudaEventDisableTiming);
        cudaEventCreateWithFlags(&g_ev_join, cudaEventDisableTiming);
        cudaEventCreateWithFlags(&g_ev_ns,   cudaEventDisableTiming);
    }
};
StreamInit g_stream_init;
}

// ---------------- cp.async helpers ----------------
__device__ __forceinline__ void cp_async16(void* dst, const void* src, int ssize) {
    asm volatile("cp.async.cg.shared.global [%0], [%1], 16, %2;\n" ::
        "r"((unsigned)__cvta_generic_to_shared(dst)), "l"(src), "r"(ssize));
}
__device__ __forceinline__ void cp_commit() {
    asm volatile("cp.async.commit_group;\n" ::: "memory");
}
__device__ __forceinline__ void cp_wait_all() {
    asm volatile("cp.async.wait_group 0;\n" ::: "memory");
}

__device__ __forceinline__ unsigned packh2(float lo, float hi) {
    __half2 h = __floats2half2_rn(lo, hi);
    return *(unsigned*)&h;
}

// ---------------- degree / norm / CSR build ----------------
__global__ void k_count(const int* __restrict__ src, const int* __restrict__ dst) {
    int e = blockIdx.x * blockDim.x + threadIdx.x;
    if (e < N_EDGES) {
        atomicAdd(&g_deg_out[src[e]], 1);
        atomicAdd(&g_deg_in [dst[e]], 1);
    }
}

// fused: block scan + atomic block base + cursor/norm write
__global__ void k_scan_fused() {
    __shared__ int s[1024];
    __shared__ int base_sh;
    int i = blockIdx.x * 1024 + threadIdx.x;
    int di = (i < N_NODES) ? g_deg_in[i] : 0;
    s[threadIdx.x] = di;
    __syncthreads();
    for (int off = 1; off < 1024; off <<= 1) {
        int t = (threadIdx.x >= off) ? s[threadIdx.x - off] : 0;
        __syncthreads();
        s[threadIdx.x] += t;
        __syncthreads();
    }
    if (threadIdx.x == 1023) base_sh = atomicAdd(&g_total, s[1023]);
    __syncthreads();
    if (i < N_NODES) {
        int incl = s[threadIdx.x] + base_sh;
        g_incl[i] = incl;
        g_cursor[i] = incl - di;
        int dout = g_deg_out[i];
        g_ns[i] = rsqrtf((float)(dout > 1 ? dout : 1));
        g_nd[i] = rsqrtf((float)(di   > 1 ? di   : 1));
    }
}

__global__ void k_fill(const int* __restrict__ src, const int* __restrict__ dst) {
    int e = blockIdx.x * blockDim.x + threadIdx.x;
    if (e < N_EDGES) {
        int pos = atomicAdd(&g_cursor[dst[e]], 1);
        g_csr[pos] = src[e];
    }
}

// ---------------- weight convert ----------------
__global__ void k_cvtW(const float* __restrict__ W1, const float* __restrict__ W2) {
    int i = blockIdx.x * blockDim.x + threadIdx.x;
    int tot1 = 128 * NFEATP;
    if (i < tot1) {
        int n = i / NFEATP, k = i % NFEATP;
        float v = (k < NFEAT) ? W1[(long)k * HID + n] : 0.f;
        g_w1ht[n][k] = __float2half_rn(v);
    } else {
        int j = i - tot1;
        if (j < 64 * HID) {
            int n = j / HID, k = j % HID;
            float v = (n < NCLS) ? W2[(long)k * NCLS + n] : 0.f;
            g_w2ht[n][k] = __float2half_rn(v);
        }
    }
}

// ---------------- ns pre-scale: h1h[row] *= ns[row]  (removes ns from agg1 edge loop) --
__global__ void k_scale_ns() {
    int idx = blockIdx.x * blockDim.x + threadIdx.x;      // one uint2 = 4 halves
    if (idx >= N_NODES * 32) return;
    int row = idx >> 5;
    float nsv = g_ns[row];
    uint2* p = (uint2*)g_h1h + idx;
    uint2 u = *p;
    float2 f0 = __half22float2(*(const __half2*)&u.x);
    float2 f1 = __half22float2(*(const __half2*)&u.y);
    u.x = packh2(f0.x * nsv, f0.y * nsv);
    u.y = packh2(f1.x * nsv, f1.y * nsv);
    *p = u;
}

// ---------------- GEMM1 fp16 HMMA: h1h = fp16(x @ W1) -------
#define G1_AS_BYTES (2 * 128 * 40 * 2)
#define G1_BS_BYTES (2 * 128 * 40 * 2)
#define G1_SMEM     (G1_AS_BYTES + G1_BS_BYTES)

__global__ __launch_bounds__(256, 2)
void k_gemm1_f16(const float* __restrict__ A, __half* __restrict__ out, int M) {
    extern __shared__ char smem_raw[];
    __half (*As)[128][40] = (__half(*)[128][40])smem_raw;
    __half (*Bs)[128][40] = (__half(*)[128][40])(smem_raw + G1_AS_BYTES);

    const int tid  = threadIdx.x;
    const int lane = tid & 31;
    const int w    = tid >> 5;
    const int wm   = w >> 1;
    const int wn   = w & 1;
    const int g    = lane >> 2;
    const int tig  = lane & 3;
    const int rowbase = blockIdx.y * 128;

    float acc[2][8][4];
#pragma unroll
    for (int mi = 0; mi < 2; mi++)
#pragma unroll
        for (int ni = 0; ni < 8; ni++)
#pragma unroll
            for (int j = 0; j < 4; j++) acc[mi][ni][j] = 0.f;

    float4 aReg[4];
    const int am = tid >> 3;
    const int ac = tid & 7;

    auto loadA = [&](int k0) {
#pragma unroll
        for (int i = 0; i < 4; i++) {
            int m = am + i * 32;
            int gm = rowbase + m;
            int k = k0 + ac * 4;
            float4 v = make_float4(0.f, 0.f, 0.f, 0.f);
            if (gm < M) {
                const float* p = A + (long)gm * NFEAT + k;
                if (k + 3 < NFEAT) {
                    float2 lo = *(const float2*)p;
                    float2 hi = *(const float2*)(p + 2);
                    v.x = lo.x; v.y = lo.y; v.z = hi.x; v.w = hi.y;
                } else if (k + 1 < NFEAT) {
                    float2 lo = *(const float2*)p;
                    v.x = lo.x; v.y = lo.y;
                }
            }
            aReg[i] = v;
        }
    };
    auto stsA = [&](int b) {
#pragma unroll
        for (int i = 0; i < 4; i++) {
            int m = am + i * 32;
            uint2 u;
            u.x = packh2(aReg[i].x, aReg[i].y);
            u.y = packh2(aReg[i].z, aReg[i].w);
            *(uint2*)&As[b][m][ac * 4] = u;
        }
    };
    auto issueB = [&](int k0, int b) {
#pragma unroll
        for (int i = 0; i < 2; i++) {
            int idx = tid + i * 256;
            int n = idx >> 2, c = idx & 3;
            cp_async16(&Bs[b][n][c * 8], &g_w1ht[n][k0 + c * 8], 16);
        }
    };

    const int NIT = NFEATP / 32;   // 19

    loadA(0);
    issueB(0, 0); cp_commit();
    stsA(0);
    loadA(32);

    for (int it = 0; it < NIT; it++) {
        const int cur = it & 1;
        cp_wait_all();
        __syncthreads();
        if (it + 1 < NIT) {
            stsA(cur ^ 1);
            issueB((it + 1) * 32, cur ^ 1);
            cp_commit();
        }
        if (it + 2 < NIT) loadA((it + 2) * 32);

#pragma unroll
        for (int kk = 0; kk < 32; kk += 16) {
            unsigned afr[2][4];
#pragma unroll
            for (int mi = 0; mi < 2; mi++) {
                int mb = wm * 32 + mi * 16;
                afr[mi][0] = *(const unsigned*)&As[cur][mb + g    ][kk + tig * 2];
                afr[mi][1] = *(const unsigned*)&As[cur][mb + g + 8][kk + tig * 2];
                afr[mi][2] = *(const unsigned*)&As[cur][mb + g    ][kk + tig * 2 + 8];
                afr[mi][3] = *(const unsigned*)&As[cur][mb + g + 8][kk + tig * 2 + 8];
            }
            unsigned bfr[8][2];
#pragma unroll
            for (int ni = 0; ni < 8; ni++) {
                int nb = wn * 64 + ni * 8 + g;
                bfr[ni][0] = *(const unsigned*)&Bs[cur][nb][kk + tig * 2];
                bfr[ni][1] = *(const unsigned*)&Bs[cur][nb][kk + tig * 2 + 8];
            }
#pragma unroll
            for (int mi = 0; mi < 2; mi++)
#pragma unroll
                for (int ni = 0; ni < 8; ni++) {
                    asm volatile(
                        "mma.sync.aligned.m16n8k16.row.col.f32.f16.f16.f32 "
                        "{%0,%1,%2,%3}, {%4,%5,%6,%7}, {%8,%9}, {%0,%1,%2,%3};"
                        : "+f"(acc[mi][ni][0]), "+f"(acc[mi][ni][1]),
                          "+f"(acc[mi][ni][2]), "+f"(acc[mi][ni][3])
                        : "r"(afr[mi][0]), "r"(afr[mi][1]),
                          "r"(afr[mi][2]), "r"(afr[mi][3]),
                          "r"(bfr[ni][0]), "r"(bfr[ni][1]));
                }
        }
    }

#pragma unroll
    for (int mi = 0; mi < 2; mi++) {
        int row0 = rowbase + wm * 32 + mi * 16 + g;
        int row1 = row0 + 8;
#pragma unroll
        for (int ni = 0; ni < 8; ni++) {
            int col = wn * 64 + ni * 8 + tig * 2;
            if (row0 < M)
                *(__half2*)(out + (long)row0 * HID + col) =
                    __floats2half2_rn(acc[mi][ni][0], acc[mi][ni][1]);
            if (row1 < M)
                *(__half2*)(out + (long)row1 * HID + col) =
                    __floats2half2_rn(acc[mi][ni][2], acc[mi][ni][3]);
        }
    }
}

// ---------------- GEMM2 fp16 HMMA: h2h = fp16( ns[row] * (h1bh @ W2) ) ----------------
__global__ __launch_bounds__(256, 2)
void k_gemm2_f16(const float* __restrict__ ns, __half* __restrict__ out, int M) {
    __shared__ __half As[2][128][40];
    __shared__ __half Bs[2][64][40];

    const int tid  = threadIdx.x;
    const int lane = tid & 31;
    const int w    = tid >> 5;
    const int wm   = w >> 1;
    const int wn   = w & 1;
    const int g    = lane >> 2;
    const int tig  = lane & 3;
    const int rowbase = blockIdx.y * 128;

    float acc[2][4][4];
#pragma unroll
    for (int mi = 0; mi < 2; mi++)
#pragma unroll
        for (int ni = 0; ni < 4; ni++)
#pragma unroll
            for (int j = 0; j < 4; j++) acc[mi][ni][j] = 0.f;

    auto issueA = [&](int k0, int b) {
#pragma unroll
        for (int i = 0; i < 2; i++) {
            int idx = tid + i * 256;
            int m = idx >> 2, c = idx & 3;
            int gm = rowbase + m;
            int valid = (gm < M);
            const __half* src = g_h1bh + (valid ? ((size_t)gm * HID + k0 + c * 8) : 0);
            cp_async16(&As[b][m][c * 8], src, valid ? 16 : 0);
        }
    };
    auto issueB = [&](int k0, int b) {
        int n = tid >> 2, c = tid & 3;
        cp_async16(&Bs[b][n][c * 8], &g_w2ht[n][k0 + c * 8], 16);
    };

    const int NIT = HID / 32;   // 4

    issueA(0, 0); issueB(0, 0); cp_commit();

    for (int it = 0; it < NIT; it++) {
        const int cur = it & 1;
        cp_wait_all();
        __syncthreads();
        if (it + 1 < NIT) {
            issueA((it + 1) * 32, cur ^ 1);
            issueB((it + 1) * 32, cur ^ 1);
            cp_commit();
        }

#pragma unroll
        for (int kk = 0; kk < 32; kk += 16) {
            unsigned afr[2][4];
#pragma unroll
            for (int mi = 0; mi < 2; mi++) {
                int mb = wm * 32 + mi * 16;
                afr[mi][0] = *(const unsigned*)&As[cur][mb + g    ][kk + tig * 2];
                afr[mi][1] = *(const unsigned*)&As[cur][mb + g + 8][kk + tig * 2];
                afr[mi][2] = *(const unsigned*)&As[cur][mb + g    ][kk + tig * 2 + 8];
                afr[mi][3] = *(const unsigned*)&As[cur][mb + g + 8][kk + tig * 2 + 8];
            }
            unsigned bfr[4][2];
#pragma unroll
            for (int ni = 0; ni < 4; ni++) {
                int nb = wn * 32 + ni * 8 + g;
                bfr[ni][0] = *(const unsigned*)&Bs[cur][nb][kk + tig * 2];
                bfr[ni][1] = *(const unsigned*)&Bs[cur][nb][kk + tig * 2 + 8];
            }
#pragma unroll
            for (int mi = 0; mi < 2; mi++)
#pragma unroll
                for (int ni = 0; ni < 4; ni++) {
                    asm volatile(
                        "mma.sync.aligned.m16n8k16.row.col.f32.f16.f16.f32 "
                        "{%0,%1,%2,%3}, {%4,%5,%6,%7}, {%8,%9}, {%0,%1,%2,%3};"
                        : "+f"(acc[mi][ni][0]), "+f"(acc[mi][ni][1]),
                          "+f"(acc[mi][ni][2]), "+f"(acc[mi][ni][3])
                        : "r"(afr[mi][0]), "r"(afr[mi][1]),
                          "r"(afr[mi][2]), "r"(afr[mi][3]),
                          "r"(bfr[ni][0]), "r"(bfr[ni][1]));
                }
        }
    }

#pragma unroll
    for (int mi = 0; mi < 2; mi++) {
        int row0 = rowbase + wm * 32 + mi * 16 + g;
        int row1 = row0 + 8;
        float s0 = (row0 < M) ? ns[row0] : 0.f;
        float s1 = (row1 < M) ? ns[row1] : 0.f;
#pragma unroll
        for (int ni = 0; ni < 4; ni++) {
            int col = wn * 32 + ni * 8 + tig * 2;
            if (col <= 40) {
                if (row0 < M)
                    *(__half2*)(out + (long)row0 * H2S + col) =
                        __floats2half2_rn(acc[mi][ni][0] * s0, acc[mi][ni][1] * s0);
                if (row1 < M)
                    *(__half2*)(out + (long)row1 * H2S + col) =
                        __floats2half2_rn(acc[mi][ni][2] * s1, acc[mi][ni][3] * s1);
            }
        }
    }
}

// ---------------- layer-1 aggregation: warp/node fp16 gather (unroll-8), pure adds ----
__global__ void k_agg1(const float* __restrict__ b1) {
    int node = (blockIdx.x * blockDim.x + threadIdx.x) >> 5;
    int lane = threadIdx.x & 31;
    if (node >= N_NODES) return;
    int end = g_incl[node];
    int j = end - g_deg_in[node];
    float a0 = 0.f, a1 = 0.f, a2 = 0.f, a3 = 0.f;

    auto body = [&](int s) {
        uint2 u = *((const uint2*)(g_h1h + (size_t)s * HID) + lane);
        float2 f0 = __half22float2(*(const __half2*)&u.x);
        float2 f1 = __half22float2(*(const __half2*)&u.y);
        a0 += f0.x; a1 += f0.y; a2 += f1.x; a3 += f1.y;
    };

    for (; j + 8 <= end; j += 8) {
        int s0 = g_csr[j],     s1 = g_csr[j + 1], s2 = g_csr[j + 2], s3 = g_csr[j + 3];
        int s4 = g_csr[j + 4], s5 = g_csr[j + 5], s6 = g_csr[j + 6], s7 = g_csr[j + 7];
        body(s0); body(s1); body(s2); body(s3);
        body(s4); body(s5); body(s6); body(s7);
    }
    for (; j < end; j++) body(g_csr[j]);

    float nd = g_nd[node];
    float4 bb = ((const float4*)b1)[lane];
    uint2 o;
    o.x = packh2(fmaxf(a0 * nd + bb.x, 0.f), fmaxf(a1 * nd + bb.y, 0.f));
    o.y = packh2(fmaxf(a2 * nd + bb.z, 0.f), fmaxf(a3 * nd + bb.w, 0.f));
    *((uint2*)(g_h1bh + (size_t)node * HID) + lane) = o;
}

// ---------------- layer-2 aggregation: warp/node fp16 gather (unroll-8), nd+bias -------
__global__ void k_agg2(const float* __restrict__ b2, float* __restrict__ out) {
    int node = (blockIdx.x * blockDim.x + threadIdx.x) >> 5;
    int lane = threadIdx.x & 31;
    if (node >= N_NODES) return;
    int end = g_incl[node];
    int j = end - g_deg_in[node];
    int c = lane * 2;
    bool act = (c < NCLS + 1);
    float a0 = 0.f, a1 = 0.f;

    auto body = [&](int s) {
        if (act) {
            float2 f = __half22float2(*(const __half2*)(g_h2h + (size_t)s * H2S + c));
            a0 += f.x; a1 += f.y;
        }
    };

    for (; j + 8 <= end; j += 8) {
        int s0 = g_csr[j],     s1 = g_csr[j + 1], s2 = g_csr[j + 2], s3 = g_csr[j + 3];
        int s4 = g_csr[j + 4], s5 = g_csr[j + 5], s6 = g_csr[j + 6], s7 = g_csr[j + 7];
        body(s0); body(s1); body(s2); body(s3);
        body(s4); body(s5); body(s6); body(s7);
    }
    for (; j < end; j++) body(g_csr[j]);

    if (act) {
        float nd = g_nd[node];
        float* po = out + (long)node * NCLS;
        po[c] = a0 * nd + b2[c];
        if (c + 1 < NCLS) po[c + 1] = a1 * nd + b2[c + 1];
    }
}

// ---------------- launcher ----------------
extern "C" void kernel_launch(void* const* d_in, const int* in_sizes, int n_in,
                              void* d_out, int out_size) {
    const float* x    = (const float*)d_in[0];
    const int*   esrc = (const int*)  d_in[1];
    const int*   edst = (const int*)  d_in[2];
    const float* W1   = (const float*)d_in[3];
    const float* b1   = (const float*)d_in[4];
    const float* W2   = (const float*)d_in[5];
    const float* b2   = (const float*)d_in[6];
    float*       out  = (float*)d_out;

    __half *p_h1h, *p_h2h;
    float  *p_ns;
    int    *p_din, *p_dout, *p_tot;
    cudaGetSymbolAddress((void**)&p_h1h, g_h1h);
    cudaGetSymbolAddress((void**)&p_h2h, g_h2h);
    cudaGetSymbolAddress((void**)&p_ns,  g_ns);
    cudaGetSymbolAddress((void**)&p_din, g_deg_in);
    cudaGetSymbolAddress((void**)&p_dout, g_deg_out);
    cudaGetSymbolAddress((void**)&p_tot, g_total);

    static bool attr_done = false;
    if (!attr_done) {
        cudaFuncSetAttribute(k_gemm1_f16,
                             cudaFuncAttributeMaxDynamicSharedMemorySize, G1_SMEM);
        attr_done = true;
    }

    const int TB = 256;

    // fork: weight-convert + GEMM1 (independent of edges) on s2; CSR chain on stream 0
    cudaEventRecord(g_ev_fork, 0);
    cudaStreamWaitEvent(g_s2, g_ev_fork, 0);
    {
        int tot = 128 * NFEATP + 64 * HID;
        k_cvtW<<<(tot + TB - 1) / TB, TB, 0, g_s2>>>(W1, W2);
        dim3 grid(1, (N_NODES + 127) / 128);
        k_gemm1_f16<<<grid, 256, G1_SMEM, g_s2>>>(x, p_h1h, N_NODES);
    }

    // CSR + norms on default stream (zeroing via capturable memsets)
    cudaMemsetAsync(p_din,  0, N_NODES * sizeof(int), 0);
    cudaMemsetAsync(p_dout, 0, N_NODES * sizeof(int), 0);
    cudaMemsetAsync(p_tot,  0, sizeof(int), 0);
    k_count   <<<(N_EDGES + TB - 1) / TB, TB>>>(esrc, edst);
    int nb = (N_NODES + 1023) / 1024;
    k_scan_fused<<<nb, 1024>>>();
    cudaEventRecord(g_ev_ns, 0);                 // ns ready
    k_fill      <<<(N_EDGES + TB - 1) / TB, TB>>>(esrc, edst);

    // s2: after GEMM1 + ns ready, pre-scale h1h rows by ns (overlaps k_fill)
    cudaStreamWaitEvent(g_s2, g_ev_ns, 0);
    k_scale_ns<<<(N_NODES * 32 + TB - 1) / TB, TB, 0, g_s2>>>();
    cudaEventRecord(g_ev_join, g_s2);

    // join: agg1 needs scaled h1h + csr + nd
    cudaStreamWaitEvent(0, g_ev_join, 0);
    k_agg1<<<(N_NODES * 32 + TB - 1) / TB, TB>>>(b1);

    // layer 2
    {
        dim3 grid(1, (N_NODES + 127) / 128);
        k_gemm2_f16<<<grid, 256>>>(p_ns, p_h2h, N_NODES);
    }
    k_agg2<<<(N_NODES * 32 + TB - 1) / TB, TB>>>(b2, out);
}

// round 16
// speedup vs baseline: 1.0470x; 1.0036x over previous
#include <cuda_runtime.h>
#include <cuda_fp16.h>
#include <cuda_bf16.h>

#define N_NODES  100000
#define N_EDGES  1600000
#define NFEAT    602
#define NFEATP   608     // padded to 19*32
#define HID      128
#define NCLS     41
#define H2S      48      // padded h2 row stride in halves (cols 41..47 pad)

// ---------------- device scratch (no allocations allowed) ----------------
__device__ int   g_deg_in[N_NODES];
__device__ int   g_deg_out[N_NODES];
__device__ float g_ns[N_NODES];          // deg_out^-1/2 (clipped)
__device__ float g_nd[N_NODES];          // deg_in^-1/2  (clipped)
__device__ int   g_incl[N_NODES];        // end offset of node's csr bucket
__device__ int   g_total;                // atomic base allocator for fused scan
__device__ int   g_cursor[N_NODES];
__device__ int   g_csr[N_EDGES];         // src ids grouped by dst
__device__ __align__(16) __half g_h1h [(size_t)N_NODES * HID];  // raw x@W1 (no ns), fp16
__device__ __align__(16) __half g_h1bh[(size_t)N_NODES * HID];  // relu'd layer-1 out, fp16
__device__ __align__(16) __half g_h2h [(size_t)N_NODES * H2S];  // ns*(h1b@W2), fp16
__device__ __align__(16) __half g_w1ht[128][NFEATP];            // W1^T fp16, zero-padded
__device__ __align__(16) __half g_w2ht[64][HID];                // W2^T fp16, zero-padded

// ---------------- streams/events (created before harness baseline) ----
static cudaStream_t g_s2;
static cudaEvent_t  g_ev_fork, g_ev_join;
namespace {
struct StreamInit {
    StreamInit() {
        cudaStreamCreateWithFlags(&g_s2, cudaStreamNonBlocking);
        cudaEventCreateWithFlags(&g_ev_fork, cudaEventDisableTiming);
        cudaEventCreateWithFlags(&g_ev_join, cudaEventDisableTiming);
    }
};
StreamInit g_stream_init;
}

// ---------------- cp.async helpers ----------------
__device__ __forceinline__ void cp_async16(void* dst, const void* src, int ssize) {
    asm volatile("cp.async.cg.shared.global [%0], [%1], 16, %2;\n" ::
        "r"((unsigned)__cvta_generic_to_shared(dst)), "l"(src), "r"(ssize));
}
__device__ __forceinline__ void cp_commit() {
    asm volatile("cp.async.commit_group;\n" ::: "memory");
}
__device__ __forceinline__ void cp_wait_all() {
    asm volatile("cp.async.wait_group 0;\n" ::: "memory");
}

__device__ __forceinline__ unsigned packh2(float lo, float hi) {
    __half2 h = __floats2half2_rn(lo, hi);
    return *(unsigned*)&h;
}

// ---------------- degree / norm / CSR build ----------------
__global__ void k_count(const int* __restrict__ src, const int* __restrict__ dst) {
    int e = blockIdx.x * blockDim.x + threadIdx.x;
    if (e < N_EDGES) {
        atomicAdd(&g_deg_out[src[e]], 1);
        atomicAdd(&g_deg_in [dst[e]], 1);
    }
}

// fused: block scan + atomic block base + cursor/norm write
__global__ void k_scan_fused() {
    __shared__ int s[1024];
    __shared__ int base_sh;
    int i = blockIdx.x * 1024 + threadIdx.x;
    int di = (i < N_NODES) ? g_deg_in[i] : 0;
    s[threadIdx.x] = di;
    __syncthreads();
    for (int off = 1; off < 1024; off <<= 1) {
        int t = (threadIdx.x >= off) ? s[threadIdx.x - off] : 0;
        __syncthreads();
        s[threadIdx.x] += t;
        __syncthreads();
    }
    if (threadIdx.x == 1023) base_sh = atomicAdd(&g_total, s[1023]);
    __syncthreads();
    if (i < N_NODES) {
        int incl = s[threadIdx.x] + base_sh;
        g_incl[i] = incl;
        g_cursor[i] = incl - di;
        int dout = g_deg_out[i];
        g_ns[i] = rsqrtf((float)(dout > 1 ? dout : 1));
        g_nd[i] = rsqrtf((float)(di   > 1 ? di   : 1));
    }
}

__global__ void k_fill(const int* __restrict__ src, const int* __restrict__ dst) {
    int e = blockIdx.x * blockDim.x + threadIdx.x;
    if (e < N_EDGES) {
        int pos = atomicAdd(&g_cursor[dst[e]], 1);
        g_csr[pos] = src[e];
    }
}

// ---------------- weight convert ----------------
__global__ void k_cvtW(const float* __restrict__ W1, const float* __restrict__ W2) {
    int i = blockIdx.x * blockDim.x + threadIdx.x;
    int tot1 = 128 * NFEATP;
    if (i < tot1) {
        int n = i / NFEATP, k = i % NFEATP;
        float v = (k < NFEAT) ? W1[(long)k * HID + n] : 0.f;
        g_w1ht[n][k] = __float2half_rn(v);
    } else {
        int j = i - tot1;
        if (j < 64 * HID) {
            int n = j / HID, k = j % HID;
            float v = (n < NCLS) ? W2[(long)k * NCLS + n] : 0.f;
            g_w2ht[n][k] = __float2half_rn(v);
        }
    }
}

// ---------------- GEMM1 fp16 HMMA: h1h = fp16(x @ W1)  (raw; ns applied in agg1) -----
#define G1_AS_BYTES (2 * 128 * 40 * 2)
#define G1_BS_BYTES (2 * 128 * 40 * 2)
#define G1_SMEM     (G1_AS_BYTES + G1_BS_BYTES)

__global__ __launch_bounds__(256, 2)
void k_gemm1_f16(const float* __restrict__ A, __half* __restrict__ out, int M) {
    extern __shared__ char smem_raw[];
    __half (*As)[128][40] = (__half(*)[128][40])smem_raw;
    __half (*Bs)[128][40] = (__half(*)[128][40])(smem_raw + G1_AS_BYTES);

    const int tid  = threadIdx.x;
    const int lane = tid & 31;
    const int w    = tid >> 5;
    const int wm   = w >> 1;
    const int wn   = w & 1;
    const int g    = lane >> 2;
    const int tig  = lane & 3;
    const int rowbase = blockIdx.y * 128;

    float acc[2][8][4];
#pragma unroll
    for (int mi = 0; mi < 2; mi++)
#pragma unroll
        for (int ni = 0; ni < 8; ni++)
#pragma unroll
            for (int j = 0; j < 4; j++) acc[mi][ni][j] = 0.f;

    float4 aReg[4];
    const int am = tid >> 3;
    const int ac = tid & 7;

    auto loadA = [&](int k0) {
#pragma unroll
        for (int i = 0; i < 4; i++) {
            int m = am + i * 32;
            int gm = rowbase + m;
            int k = k0 + ac * 4;
            float4 v = make_float4(0.f, 0.f, 0.f, 0.f);
            if (gm < M) {
                const float* p = A + (long)gm * NFEAT + k;
                if (k + 3 < NFEAT) {
                    float2 lo = *(const float2*)p;
                    float2 hi = *(const float2*)(p + 2);
                    v.x = lo.x; v.y = lo.y; v.z = hi.x; v.w = hi.y;
                } else if (k + 1 < NFEAT) {
                    float2 lo = *(const float2*)p;
                    v.x = lo.x; v.y = lo.y;
                }
            }
            aReg[i] = v;
        }
    };
    auto stsA = [&](int b) {
#pragma unroll
        for (int i = 0; i < 4; i++) {
            int m = am + i * 32;
            uint2 u;
            u.x = packh2(aReg[i].x, aReg[i].y);
            u.y = packh2(aReg[i].z, aReg[i].w);
            *(uint2*)&As[b][m][ac * 4] = u;
        }
    };
    auto issueB = [&](int k0, int b) {
#pragma unroll
        for (int i = 0; i < 2; i++) {
            int idx = tid + i * 256;
            int n = idx >> 2, c = idx & 3;
            cp_async16(&Bs[b][n][c * 8], &g_w1ht[n][k0 + c * 8], 16);
        }
    };

    const int NIT = NFEATP / 32;   // 19

    loadA(0);
    issueB(0, 0); cp_commit();
    stsA(0);
    loadA(32);

    for (int it = 0; it < NIT; it++) {
        const int cur = it & 1;
        cp_wait_all();
        __syncthreads();
        if (it + 1 < NIT) {
            stsA(cur ^ 1);
            issueB((it + 1) * 32, cur ^ 1);
            cp_commit();
        }
        if (it + 2 < NIT) loadA((it + 2) * 32);

#pragma unroll
        for (int kk = 0; kk < 32; kk += 16) {
            unsigned afr[2][4];
#pragma unroll
            for (int mi = 0; mi < 2; mi++) {
                int mb = wm * 32 + mi * 16;
                afr[mi][0] = *(const unsigned*)&As[cur][mb + g    ][kk + tig * 2];
                afr[mi][1] = *(const unsigned*)&As[cur][mb + g + 8][kk + tig * 2];
                afr[mi][2] = *(const unsigned*)&As[cur][mb + g    ][kk + tig * 2 + 8];
                afr[mi][3] = *(const unsigned*)&As[cur][mb + g + 8][kk + tig * 2 + 8];
            }
            unsigned bfr[8][2];
#pragma unroll
            for (int ni = 0; ni < 8; ni++) {
                int nb = wn * 64 + ni * 8 + g;
                bfr[ni][0] = *(const unsigned*)&Bs[cur][nb][kk + tig * 2];
                bfr[ni][1] = *(const unsigned*)&Bs[cur][nb][kk + tig * 2 + 8];
            }
#pragma unroll
            for (int mi = 0; mi < 2; mi++)
#pragma unroll
                for (int ni = 0; ni < 8; ni++) {
                    asm volatile(
                        "mma.sync.aligned.m16n8k16.row.col.f32.f16.f16.f32 "
                        "{%0,%1,%2,%3}, {%4,%5,%6,%7}, {%8,%9}, {%0,%1,%2,%3};"
                        : "+f"(acc[mi][ni][0]), "+f"(acc[mi][ni][1]),
                          "+f"(acc[mi][ni][2]), "+f"(acc[mi][ni][3])
                        : "r"(afr[mi][0]), "r"(afr[mi][1]),
                          "r"(afr[mi][2]), "r"(afr[mi][3]),
                          "r"(bfr[ni][0]), "r"(bfr[ni][1]));
                }
        }
    }

#pragma unroll
    for (int mi = 0; mi < 2; mi++) {
        int row0 = rowbase + wm * 32 + mi * 16 + g;
        int row1 = row0 + 8;
#pragma unroll
        for (int ni = 0; ni < 8; ni++) {
            int col = wn * 64 + ni * 8 + tig * 2;
            if (row0 < M)
                *(__half2*)(out + (long)row0 * HID + col) =
                    __floats2half2_rn(acc[mi][ni][0], acc[mi][ni][1]);
            if (row1 < M)
                *(__half2*)(out + (long)row1 * HID + col) =
                    __floats2half2_rn(acc[mi][ni][2], acc[mi][ni][3]);
        }
    }
}

// ---------------- GEMM2 fp16 HMMA: h2h = fp16( ns[row] * (h1bh @ W2) ) ----------------
__global__ __launch_bounds__(256, 2)
void k_gemm2_f16(const float* __restrict__ ns, __half* __restrict__ out, int M) {
    __shared__ __half As[2][128][40];
    __shared__ __half Bs[2][64][40];

    const int tid  = threadIdx.x;
    const int lane = tid & 31;
    const int w    = tid >> 5;
    const int wm   = w >> 1;
    const int wn   = w & 1;
    const int g    = lane >> 2;
    const int tig  = lane & 3;
    const int rowbase = blockIdx.y * 128;

    float acc[2][4][4];
#pragma unroll
    for (int mi = 0; mi < 2; mi++)
#pragma unroll
        for (int ni = 0; ni < 4; ni++)
#pragma unroll
            for (int j = 0; j < 4; j++) acc[mi][ni][j] = 0.f;

    auto issueA = [&](int k0, int b) {
#pragma unroll
        for (int i = 0; i < 2; i++) {
            int idx = tid + i * 256;
            int m = idx >> 2, c = idx & 3;
            int gm = rowbase + m;
            int valid = (gm < M);
            const __half* src = g_h1bh + (valid ? ((size_t)gm * HID + k0 + c * 8) : 0);
            cp_async16(&As[b][m][c * 8], src, valid ? 16 : 0);
        }
    };
    auto issueB = [&](int k0, int b) {
        int n = tid >> 2, c = tid & 3;
        cp_async16(&Bs[b][n][c * 8], &g_w2ht[n][k0 + c * 8], 16);
    };

    const int NIT = HID / 32;   // 4

    issueA(0, 0); issueB(0, 0); cp_commit();

    for (int it = 0; it < NIT; it++) {
        const int cur = it & 1;
        cp_wait_all();
        __syncthreads();
        if (it + 1 < NIT) {
            issueA((it + 1) * 32, cur ^ 1);
            issueB((it + 1) * 32, cur ^ 1);
            cp_commit();
        }

#pragma unroll
        for (int kk = 0; kk < 32; kk += 16) {
            unsigned afr[2][4];
#pragma unroll
            for (int mi = 0; mi < 2; mi++) {
                int mb = wm * 32 + mi * 16;
                afr[mi][0] = *(const unsigned*)&As[cur][mb + g    ][kk + tig * 2];
                afr[mi][1] = *(const unsigned*)&As[cur][mb + g + 8][kk + tig * 2];
                afr[mi][2] = *(const unsigned*)&As[cur][mb + g    ][kk + tig * 2 + 8];
                afr[mi][3] = *(const unsigned*)&As[cur][mb + g + 8][kk + tig * 2 + 8];
            }
            unsigned bfr[4][2];
#pragma unroll
            for (int ni = 0; ni < 4; ni++) {
                int nb = wn * 32 + ni * 8 + g;
                bfr[ni][0] = *(const unsigned*)&Bs[cur][nb][kk + tig * 2];
                bfr[ni][1] = *(const unsigned*)&Bs[cur][nb][kk + tig * 2 + 8];
            }
#pragma unroll
            for (int mi = 0; mi < 2; mi++)
#pragma unroll
                for (int ni = 0; ni < 4; ni++) {
                    asm volatile(
                        "mma.sync.aligned.m16n8k16.row.col.f32.f16.f16.f32 "
                        "{%0,%1,%2,%3}, {%4,%5,%6,%7}, {%8,%9}, {%0,%1,%2,%3};"
                        : "+f"(acc[mi][ni][0]), "+f"(acc[mi][ni][1]),
                          "+f"(acc[mi][ni][2]), "+f"(acc[mi][ni][3])
                        : "r"(afr[mi][0]), "r"(afr[mi][1]),
                          "r"(afr[mi][2]), "r"(afr[mi][3]),
                          "r"(bfr[ni][0]), "r"(bfr[ni][1]));
                }
        }
    }

#pragma unroll
    for (int mi = 0; mi < 2; mi++) {
        int row0 = rowbase + wm * 32 + mi * 16 + g;
        int row1 = row0 + 8;
        float s0 = (row0 < M) ? ns[row0] : 0.f;
        float s1 = (row1 < M) ? ns[row1] : 0.f;
#pragma unroll
        for (int ni = 0; ni < 4; ni++) {
            int col = wn * 32 + ni * 8 + tig * 2;
            if (col <= 40) {
                if (row0 < M)
                    *(__half2*)(out + (long)row0 * H2S + col) =
                        __floats2half2_rn(acc[mi][ni][0] * s0, acc[mi][ni][1] * s0);
                if (row1 < M)
                    *(__half2*)(out + (long)row1 * H2S + col) =
                        __floats2half2_rn(acc[mi][ni][2] * s1, acc[mi][ni][3] * s1);
            }
        }
    }
}

// ---------------- layer-1 aggregation: warp/node fp16 gather (unroll-8), ns[src] fused --
__global__ void k_agg1(const float* __restrict__ b1) {
    int node = (blockIdx.x * blockDim.x + threadIdx.x) >> 5;
    int lane = threadIdx.x & 31;
    if (node >= N_NODES) return;
    int end = g_incl[node];
    int j = end - g_deg_in[node];
    float a0 = 0.f, a1 = 0.f, a2 = 0.f, a3 = 0.f;

    auto body = [&](int s) {
        float nsv = g_ns[s];
        uint2 u = *((const uint2*)(g_h1h + (size_t)s * HID) + lane);
        float2 f0 = __half22float2(*(const __half2*)&u.x);
        float2 f1 = __half22float2(*(const __half2*)&u.y);
        a0 = fmaf(nsv, f0.x, a0);
        a1 = fmaf(nsv, f0.y, a1);
        a2 = fmaf(nsv, f1.x, a2);
        a3 = fmaf(nsv, f1.y, a3);
    };

    for (; j + 8 <= end; j += 8) {
        int s0 = g_csr[j],     s1 = g_csr[j + 1], s2 = g_csr[j + 2], s3 = g_csr[j + 3];
        int s4 = g_csr[j + 4], s5 = g_csr[j + 5], s6 = g_csr[j + 6], s7 = g_csr[j + 7];
        body(s0); body(s1); body(s2); body(s3);
        body(s4); body(s5); body(s6); body(s7);
    }
    for (; j < end; j++) body(g_csr[j]);

    float nd = g_nd[node];
    float4 bb = ((const float4*)b1)[lane];
    uint2 o;
    o.x = packh2(fmaxf(a0 * nd + bb.x, 0.f), fmaxf(a1 * nd + bb.y, 0.f));
    o.y = packh2(fmaxf(a2 * nd + bb.z, 0.f), fmaxf(a3 * nd + bb.w, 0.f));
    *((uint2*)(g_h1bh + (size_t)node * HID) + lane) = o;
}

// ---------------- layer-2 aggregation: warp/node fp16 gather (unroll-8), nd+bias -------
__global__ void k_agg2(const float* __restrict__ b2, float* __restrict__ out) {
    int node = (blockIdx.x * blockDim.x + threadIdx.x) >> 5;
    int lane = threadIdx.x & 31;
    if (node >= N_NODES) return;
    int end = g_incl[node];
    int j = end - g_deg_in[node];
    int c = lane * 2;
    bool act = (c < NCLS + 1);
    float a0 = 0.f, a1 = 0.f;

    auto body = [&](int s) {
        if (act) {
            float2 f = __half22float2(*(const __half2*)(g_h2h + (size_t)s * H2S + c));
            a0 += f.x; a1 += f.y;
        }
    };

    for (; j + 8 <= end; j += 8) {
        int s0 = g_csr[j],     s1 = g_csr[j + 1], s2 = g_csr[j + 2], s3 = g_csr[j + 3];
        int s4 = g_csr[j + 4], s5 = g_csr[j + 5], s6 = g_csr[j + 6], s7 = g_csr[j + 7];
        body(s0); body(s1); body(s2); body(s3);
        body(s4); body(s5); body(s6); body(s7);
    }
    for (; j < end; j++) body(g_csr[j]);

    if (act) {
        float nd = g_nd[node];
        float* po = out + (long)node * NCLS;
        po[c] = a0 * nd + b2[c];
        if (c + 1 < NCLS) po[c + 1] = a1 * nd + b2[c + 1];
    }
}

// ---------------- launcher ----------------
extern "C" void kernel_launch(void* const* d_in, const int* in_sizes, int n_in,
                              void* d_out, int out_size) {
    const float* x    = (const float*)d_in[0];
    const int*   esrc = (const int*)  d_in[1];
    const int*   edst = (const int*)  d_in[2];
    const float* W1   = (const float*)d_in[3];
    const float* b1   = (const float*)d_in[4];
    const float* W2   = (const float*)d_in[5];
    const float* b2   = (const float*)d_in[6];
    float*       out  = (float*)d_out;

    __half *p_h1h, *p_h2h;
    float  *p_ns;
    int    *p_din, *p_dout, *p_tot;
    cudaGetSymbolAddress((void**)&p_h1h, g_h1h);
    cudaGetSymbolAddress((void**)&p_h2h, g_h2h);
    cudaGetSymbolAddress((void**)&p_ns,  g_ns);
    cudaGetSymbolAddress((void**)&p_din, g_deg_in);
    cudaGetSymbolAddress((void**)&p_dout, g_deg_out);
    cudaGetSymbolAddress((void**)&p_tot, g_total);

    static bool attr_done = false;
    if (!attr_done) {
        cudaFuncSetAttribute(k_gemm1_f16,
                             cudaFuncAttributeMaxDynamicSharedMemorySize, G1_SMEM);
        attr_done = true;
    }

    const int TB = 256;

    // fork: weight-convert + GEMM1 (independent of edges) on s2; CSR chain on stream 0
    cudaEventRecord(g_ev_fork, 0);
    cudaStreamWaitEvent(g_s2, g_ev_fork, 0);
    {
        int tot = 128 * NFEATP + 64 * HID;
        k_cvtW<<<(tot + TB - 1) / TB, TB, 0, g_s2>>>(W1, W2);
        dim3 grid(1, (N_NODES + 127) / 128);
        k_gemm1_f16<<<grid, 256, G1_SMEM, g_s2>>>(x, p_h1h, N_NODES);
    }
    cudaEventRecord(g_ev_join, g_s2);

    // CSR + norms on default stream (zeroing via capturable memsets)
    cudaMemsetAsync(p_din,  0, N_NODES * sizeof(int), 0);
    cudaMemsetAsync(p_dout, 0, N_NODES * sizeof(int), 0);
    cudaMemsetAsync(p_tot,  0, sizeof(int), 0);
    k_count   <<<(N_EDGES + TB - 1) / TB, TB>>>(esrc, edst);
    int nb = (N_NODES + 1023) / 1024;
    k_scan_fused<<<nb, 1024>>>();
    k_fill      <<<(N_EDGES + TB - 1) / TB, TB>>>(esrc, edst);

    // join: agg1 needs h1h + csr + ns + nd
    cudaStreamWaitEvent(0, g_ev_join, 0);
    k_agg1<<<(N_NODES * 32 + TB - 1) / TB, TB>>>(b1);

    // layer 2
    {
        dim3 grid(1, (N_NODES + 127) / 128);
        k_gemm2_f16<<<grid, 256>>>(p_ns, p_h2h, N_NODES);
    }
    k_agg2<<<(N_NODES * 32 + TB - 1) / TB, TB>>>(b2, out);
}

// round 17
// speedup vs baseline: 1.0744x; 1.0261x over previous
#include <cuda_runtime.h>
#include <cuda_fp16.h>
#include <cuda_bf16.h>

#define N_NODES  100000
#define N_EDGES  1600000
#define NFEAT    602
#define NFEATP   608     // padded to 19*32
#define HID      128
#define NCLS     41
#define H2S      48      // padded h2 row stride in halves (cols 41..47 pad)

// ---------------- device scratch (no allocations allowed) ----------------
__device__ int   g_deg_in[N_NODES];
__device__ int   g_deg_out[N_NODES];
__device__ float g_ns[N_NODES];          // deg_out^-1/2 (clipped)
__device__ float g_nd[N_NODES];          // deg_in^-1/2  (clipped)
__device__ int   g_incl[N_NODES];        // end offset of node's csr bucket
__device__ int   g_total;                // atomic base allocator for fused scan
__device__ int   g_cursor[N_NODES];
__device__ int   g_csr[N_EDGES];         // src ids grouped by dst
__device__ __align__(16) __half g_h1h [(size_t)N_NODES * HID];  // raw x@W1 (no ns), fp16
__device__ __align__(16) __half g_h1bh[(size_t)N_NODES * HID];  // relu'd layer-1 out, fp16
__device__ __align__(16) __half g_h2h [(size_t)N_NODES * H2S];  // ns*(h1b@W2), fp16
__device__ __align__(16) __half g_w1ht[128][NFEATP];            // W1^T fp16, zero-padded
__device__ __align__(16) __half g_w2ht[64][HID];                // W2^T fp16, zero-padded

// ---------------- streams/events for fork-join (created before harness baseline) ----
static cudaStream_t g_s2;
static cudaEvent_t  g_ev_fork, g_ev_join;
namespace {
struct StreamInit {
    StreamInit() {
        cudaStreamCreateWithFlags(&g_s2, cudaStreamNonBlocking);
        cudaEventCreateWithFlags(&g_ev_fork, cudaEventDisableTiming);
        cudaEventCreateWithFlags(&g_ev_join, cudaEventDisableTiming);
    }
};
StreamInit g_stream_init;
}

// ---------------- cp.async helpers ----------------
__device__ __forceinline__ void cp_async16(void* dst, const void* src, int ssize) {
    asm volatile("cp.async.cg.shared.global [%0], [%1], 16, %2;\n" ::
        "r"((unsigned)__cvta_generic_to_shared(dst)), "l"(src), "r"(ssize));
}
__device__ __forceinline__ void cp_commit() {
    asm volatile("cp.async.commit_group;\n" ::: "memory");
}
__device__ __forceinline__ void cp_wait_all() {
    asm volatile("cp.async.wait_group 0;\n" ::: "memory");
}

__device__ __forceinline__ unsigned packh2(float lo, float hi) {
    __half2 h = __floats2half2_rn(lo, hi);
    return *(unsigned*)&h;
}

// ---------------- degree / norm / CSR build ----------------
__global__ void k_zero_deg() {
    int i = blockIdx.x * blockDim.x + threadIdx.x;
    if (i < N_NODES) { g_deg_in[i] = 0; g_deg_out[i] = 0; }
    if (i == 0) g_total = 0;
}

__global__ void k_count(const int* __restrict__ src, const int* __restrict__ dst) {
    int e = blockIdx.x * blockDim.x + threadIdx.x;
    if (e < N_EDGES) {
        atomicAdd(&g_deg_out[src[e]], 1);
        atomicAdd(&g_deg_in [dst[e]], 1);
    }
}

// fused: block scan + atomic block base + cursor/norm write
__global__ void k_scan_fused() {
    __shared__ int s[1024];
    __shared__ int base_sh;
    int i = blockIdx.x * 1024 + threadIdx.x;
    int di = (i < N_NODES) ? g_deg_in[i] : 0;
    s[threadIdx.x] = di;
    __syncthreads();
    for (int off = 1; off < 1024; off <<= 1) {
        int t = (threadIdx.x >= off) ? s[threadIdx.x - off] : 0;
        __syncthreads();
        s[threadIdx.x] += t;
        __syncthreads();
    }
    if (threadIdx.x == 1023) base_sh = atomicAdd(&g_total, s[1023]);
    __syncthreads();
    if (i < N_NODES) {
        int incl = s[threadIdx.x] + base_sh;
        g_incl[i] = incl;
        g_cursor[i] = incl - di;
        int dout = g_deg_out[i];
        g_ns[i] = rsqrtf((float)(dout > 1 ? dout : 1));
        g_nd[i] = rsqrtf((float)(di   > 1 ? di   : 1));
    }
}

__global__ void k_fill(const int* __restrict__ src, const int* __restrict__ dst) {
    int e = blockIdx.x * blockDim.x + threadIdx.x;
    if (e < N_EDGES) {
        int pos = atomicAdd(&g_cursor[dst[e]], 1);
        g_csr[pos] = src[e];
    }
}

// ---------------- weight convert ----------------
__global__ void k_cvtW(const float* __restrict__ W1, const float* __restrict__ W2) {
    int i = blockIdx.x * blockDim.x + threadIdx.x;
    int tot1 = 128 * NFEATP;
    if (i < tot1) {
        int n = i / NFEATP, k = i % NFEATP;
        float v = (k < NFEAT) ? W1[(long)k * HID + n] : 0.f;
        g_w1ht[n][k] = __float2half_rn(v);
    } else {
        int j = i - tot1;
        if (j < 64 * HID) {
            int n = j / HID, k = j % HID;
            float v = (n < NCLS) ? W2[(long)k * NCLS + n] : 0.f;
            g_w2ht[n][k] = __float2half_rn(v);
        }
    }
}

// ---------------- GEMM1 fp16 HMMA: h1h = fp16(x @ W1)  (raw; ns applied in agg1) -----
#define G1_AS_BYTES (2 * 128 * 40 * 2)
#define G1_BS_BYTES (2 * 128 * 40 * 2)
#define G1_SMEM     (G1_AS_BYTES + G1_BS_BYTES)

__global__ __launch_bounds__(256, 2)
void k_gemm1_f16(const float* __restrict__ A, __half* __restrict__ out, int M) {
    extern __shared__ char smem_raw[];
    __half (*As)[128][40] = (__half(*)[128][40])smem_raw;
    __half (*Bs)[128][40] = (__half(*)[128][40])(smem_raw + G1_AS_BYTES);

    const int tid  = threadIdx.x;
    const int lane = tid & 31;
    const int w    = tid >> 5;
    const int wm   = w >> 1;
    const int wn   = w & 1;
    const int g    = lane >> 2;
    const int tig  = lane & 3;
    const int rowbase = blockIdx.y * 128;

    float acc[2][8][4];
#pragma unroll
    for (int mi = 0; mi < 2; mi++)
#pragma unroll
        for (int ni = 0; ni < 8; ni++)
#pragma unroll
            for (int j = 0; j < 4; j++) acc[mi][ni][j] = 0.f;

    float4 aReg[4];
    const int am = tid >> 3;
    const int ac = tid & 7;

    auto loadA = [&](int k0) {
#pragma unroll
        for (int i = 0; i < 4; i++) {
            int m = am + i * 32;
            int gm = rowbase + m;
            int k = k0 + ac * 4;
            float4 v = make_float4(0.f, 0.f, 0.f, 0.f);
            if (gm < M) {
                const float* p = A + (long)gm * NFEAT + k;
                if (k + 3 < NFEAT) {
                    float2 lo = *(const float2*)p;
                    float2 hi = *(const float2*)(p + 2);
                    v.x = lo.x; v.y = lo.y; v.z = hi.x; v.w = hi.y;
                } else if (k + 1 < NFEAT) {
                    float2 lo = *(const float2*)p;
                    v.x = lo.x; v.y = lo.y;
                }
            }
            aReg[i] = v;
        }
    };
    auto stsA = [&](int b) {
#pragma unroll
        for (int i = 0; i < 4; i++) {
            int m = am + i * 32;
            uint2 u;
            u.x = packh2(aReg[i].x, aReg[i].y);
            u.y = packh2(aReg[i].z, aReg[i].w);
            *(uint2*)&As[b][m][ac * 4] = u;
        }
    };
    auto issueB = [&](int k0, int b) {
#pragma unroll
        for (int i = 0; i < 2; i++) {
            int idx = tid + i * 256;
            int n = idx >> 2, c = idx & 3;
            cp_async16(&Bs[b][n][c * 8], &g_w1ht[n][k0 + c * 8], 16);
        }
    };

    const int NIT = NFEATP / 32;   // 19

    loadA(0);
    issueB(0, 0); cp_commit();
    stsA(0);
    loadA(32);

    for (int it = 0; it < NIT; it++) {
        const int cur = it & 1;
        cp_wait_all();
        __syncthreads();
        if (it + 1 < NIT) {
            stsA(cur ^ 1);
            issueB((it + 1) * 32, cur ^ 1);
            cp_commit();
        }
        if (it + 2 < NIT) loadA((it + 2) * 32);

#pragma unroll
        for (int kk = 0; kk < 32; kk += 16) {
            unsigned afr[2][4];
#pragma unroll
            for (int mi = 0; mi < 2; mi++) {
                int mb = wm * 32 + mi * 16;
                afr[mi][0] = *(const unsigned*)&As[cur][mb + g    ][kk + tig * 2];
                afr[mi][1] = *(const unsigned*)&As[cur][mb + g + 8][kk + tig * 2];
                afr[mi][2] = *(const unsigned*)&As[cur][mb + g    ][kk + tig * 2 + 8];
                afr[mi][3] = *(const unsigned*)&As[cur][mb + g + 8][kk + tig * 2 + 8];
            }
            unsigned bfr[8][2];
#pragma unroll
            for (int ni = 0; ni < 8; ni++) {
                int nb = wn * 64 + ni * 8 + g;
                bfr[ni][0] = *(const unsigned*)&Bs[cur][nb][kk + tig * 2];
                bfr[ni][1] = *(const unsigned*)&Bs[cur][nb][kk + tig * 2 + 8];
            }
#pragma unroll
            for (int mi = 0; mi < 2; mi++)
#pragma unroll
                for (int ni = 0; ni < 8; ni++) {
                    asm volatile(
                        "mma.sync.aligned.m16n8k16.row.col.f32.f16.f16.f32 "
                        "{%0,%1,%2,%3}, {%4,%5,%6,%7}, {%8,%9}, {%0,%1,%2,%3};"
                        : "+f"(acc[mi][ni][0]), "+f"(acc[mi][ni][1]),
                          "+f"(acc[mi][ni][2]), "+f"(acc[mi][ni][3])
                        : "r"(afr[mi][0]), "r"(afr[mi][1]),
                          "r"(afr[mi][2]), "r"(afr[mi][3]),
                          "r"(bfr[ni][0]), "r"(bfr[ni][1]));
                }
        }
    }

#pragma unroll
    for (int mi = 0; mi < 2; mi++) {
        int row0 = rowbase + wm * 32 + mi * 16 + g;
        int row1 = row0 + 8;
#pragma unroll
        for (int ni = 0; ni < 8; ni++) {
            int col = wn * 64 + ni * 8 + tig * 2;
            if (row0 < M)
                *(__half2*)(out + (long)row0 * HID + col) =
                    __floats2half2_rn(acc[mi][ni][0], acc[mi][ni][1]);
            if (row1 < M)
                *(__half2*)(out + (long)row1 * HID + col) =
                    __floats2half2_rn(acc[mi][ni][2], acc[mi][ni][3]);
        }
    }
}

// ---------------- GEMM2 fp16 HMMA: h2h = fp16( ns[row] * (h1bh @ W2) ) ----------------
__global__ __launch_bounds__(256, 2)
void k_gemm2_f16(const float* __restrict__ ns, __half* __restrict__ out, int M) {
    __shared__ __half As[2][128][40];
    __shared__ __half Bs[2][64][40];

    const int tid  = threadIdx.x;
    const int lane = tid & 31;
    const int w    = tid >> 5;
    const int wm   = w >> 1;
    const int wn   = w & 1;
    const int g    = lane >> 2;
    const int tig  = lane & 3;
    const int rowbase = blockIdx.y * 128;

    float acc[2][4][4];
#pragma unroll
    for (int mi = 0; mi < 2; mi++)
#pragma unroll
        for (int ni = 0; ni < 4; ni++)
#pragma unroll
            for (int j = 0; j < 4; j++) acc[mi][ni][j] = 0.f;

    auto issueA = [&](int k0, int b) {
#pragma unroll
        for (int i = 0; i < 2; i++) {
            int idx = tid + i * 256;
            int m = idx >> 2, c = idx & 3;
            int gm = rowbase + m;
            int valid = (gm < M);
            const __half* src = g_h1bh + (valid ? ((size_t)gm * HID + k0 + c * 8) : 0);
            cp_async16(&As[b][m][c * 8], src, valid ? 16 : 0);
        }
    };
    auto issueB = [&](int k0, int b) {
        int n = tid >> 2, c = tid & 3;
        cp_async16(&Bs[b][n][c * 8], &g_w2ht[n][k0 + c * 8], 16);
    };

    const int NIT = HID / 32;   // 4

    issueA(0, 0); issueB(0, 0); cp_commit();

    for (int it = 0; it < NIT; it++) {
        const int cur = it & 1;
        cp_wait_all();
        __syncthreads();
        if (it + 1 < NIT) {
            issueA((it + 1) * 32, cur ^ 1);
            issueB((it + 1) * 32, cur ^ 1);
            cp_commit();
        }

#pragma unroll
        for (int kk = 0; kk < 32; kk += 16) {
            unsigned afr[2][4];
#pragma unroll
            for (int mi = 0; mi < 2; mi++) {
                int mb = wm * 32 + mi * 16;
                afr[mi][0] = *(const unsigned*)&As[cur][mb + g    ][kk + tig * 2];
                afr[mi][1] = *(const unsigned*)&As[cur][mb + g + 8][kk + tig * 2];
                afr[mi][2] = *(const unsigned*)&As[cur][mb + g    ][kk + tig * 2 + 8];
                afr[mi][3] = *(const unsigned*)&As[cur][mb + g + 8][kk + tig * 2 + 8];
            }
            unsigned bfr[4][2];
#pragma unroll
            for (int ni = 0; ni < 4; ni++) {
                int nb = wn * 32 + ni * 8 + g;
                bfr[ni][0] = *(const unsigned*)&Bs[cur][nb][kk + tig * 2];
                bfr[ni][1] = *(const unsigned*)&Bs[cur][nb][kk + tig * 2 + 8];
            }
#pragma unroll
            for (int mi = 0; mi < 2; mi++)
#pragma unroll
                for (int ni = 0; ni < 4; ni++) {
                    asm volatile(
                        "mma.sync.aligned.m16n8k16.row.col.f32.f16.f16.f32 "
                        "{%0,%1,%2,%3}, {%4,%5,%6,%7}, {%8,%9}, {%0,%1,%2,%3};"
                        : "+f"(acc[mi][ni][0]), "+f"(acc[mi][ni][1]),
                          "+f"(acc[mi][ni][2]), "+f"(acc[mi][ni][3])
                        : "r"(afr[mi][0]), "r"(afr[mi][1]),
                          "r"(afr[mi][2]), "r"(afr[mi][3]),
                          "r"(bfr[ni][0]), "r"(bfr[ni][1]));
                }
        }
    }

#pragma unroll
    for (int mi = 0; mi < 2; mi++) {
        int row0 = rowbase + wm * 32 + mi * 16 + g;
        int row1 = row0 + 8;
        float s0 = (row0 < M) ? ns[row0] : 0.f;
        float s1 = (row1 < M) ? ns[row1] : 0.f;
#pragma unroll
        for (int ni = 0; ni < 4; ni++) {
            int col = wn * 32 + ni * 8 + tig * 2;
            if (col <= 40) {
                if (row0 < M)
                    *(__half2*)(out + (long)row0 * H2S + col) =
                        __floats2half2_rn(acc[mi][ni][0] * s0, acc[mi][ni][1] * s0);
                if (row1 < M)
                    *(__half2*)(out + (long)row1 * H2S + col) =
                        __floats2half2_rn(acc[mi][ni][2] * s1, acc[mi][ni][3] * s1);
            }
        }
    }
}

// ---------------- layer-1 aggregation: warp/node fp16 gather (unroll-8), ns[src] fused --
__global__ void k_agg1(const float* __restrict__ b1) {
    int node = (blockIdx.x * blockDim.x + threadIdx.x) >> 5;
    int lane = threadIdx.x & 31;
    if (node >= N_NODES) return;
    int end = g_incl[node];
    int j = end - g_deg_in[node];
    float a0 = 0.f, a1 = 0.f, a2 = 0.f, a3 = 0.f;

    auto body = [&](int s) {
        float nsv = g_ns[s];
        uint2 u = *((const uint2*)(g_h1h + (size_t)s * HID) + lane);
        float2 f0 = __half22float2(*(const __half2*)&u.x);
        float2 f1 = __half22float2(*(const __half2*)&u.y);
        a0 = fmaf(nsv, f0.x, a0);
        a1 = fmaf(nsv, f0.y, a1);
        a2 = fmaf(nsv, f1.x, a2);
        a3 = fmaf(nsv, f1.y, a3);
    };

    for (; j + 8 <= end; j += 8) {
        int s0 = g_csr[j],     s1 = g_csr[j + 1], s2 = g_csr[j + 2], s3 = g_csr[j + 3];
        int s4 = g_csr[j + 4], s5 = g_csr[j + 5], s6 = g_csr[j + 6], s7 = g_csr[j + 7];
        body(s0); body(s1); body(s2); body(s3);
        body(s4); body(s5); body(s6); body(s7);
    }
    for (; j < end; j++) body(g_csr[j]);

    float nd = g_nd[node];
    float4 bb = ((const float4*)b1)[lane];
    uint2 o;
    o.x = packh2(fmaxf(a0 * nd + bb.x, 0.f), fmaxf(a1 * nd + bb.y, 0.f));
    o.y = packh2(fmaxf(a2 * nd + bb.z, 0.f), fmaxf(a3 * nd + bb.w, 0.f));
    *((uint2*)(g_h1bh + (size_t)node * HID) + lane) = o;
}

// ---------------- layer-2 aggregation: warp/node fp16 gather (unroll-8), nd+bias -------
__global__ void k_agg2(const float* __restrict__ b2, float* __restrict__ out) {
    int node = (blockIdx.x * blockDim.x + threadIdx.x) >> 5;
    int lane = threadIdx.x & 31;
    if (node >= N_NODES) return;
    int end = g_incl[node];
    int j = end - g_deg_in[node];
    int c = lane * 2;
    bool act = (c < NCLS + 1);
    float a0 = 0.f, a1 = 0.f;

    auto body = [&](int s) {
        if (act) {
            float2 f = __half22float2(*(const __half2*)(g_h2h + (size_t)s * H2S + c));
            a0 += f.x; a1 += f.y;
        }
    };

    for (; j + 8 <= end; j += 8) {
        int s0 = g_csr[j],     s1 = g_csr[j + 1], s2 = g_csr[j + 2], s3 = g_csr[j + 3];
        int s4 = g_csr[j + 4], s5 = g_csr[j + 5], s6 = g_csr[j + 6], s7 = g_csr[j + 7];
        body(s0); body(s1); body(s2); body(s3);
        body(s4); body(s5); body(s6); body(s7);
    }
    for (; j < end; j++) body(g_csr[j]);

    if (act) {
        float nd = g_nd[node];
        float* po = out + (long)node * NCLS;
        po[c] = a0 * nd + b2[c];
        if (c + 1 < NCLS) po[c + 1] = a1 * nd + b2[c + 1];
    }
}

// ---------------- launcher ----------------
extern "C" void kernel_launch(void* const* d_in, const int* in_sizes, int n_in,
                              void* d_out, int out_size) {
    const float* x    = (const float*)d_in[0];
    const int*   esrc = (const int*)  d_in[1];
    const int*   edst = (const int*)  d_in[2];
    const float* W1   = (const float*)d_in[3];
    const float* b1   = (const float*)d_in[4];
    const float* W2   = (const float*)d_in[5];
    const float* b2   = (const float*)d_in[6];
    float*       out  = (float*)d_out;

    __half *p_h1h, *p_h2h;
    float  *p_ns;
    cudaGetSymbolAddress((void**)&p_h1h, g_h1h);
    cudaGetSymbolAddress((void**)&p_h2h, g_h2h);
    cudaGetSymbolAddress((void**)&p_ns,  g_ns);

    static bool attr_done = false;
    if (!attr_done) {
        cudaFuncSetAttribute(k_gemm1_f16,
                             cudaFuncAttributeMaxDynamicSharedMemorySize, G1_SMEM);
        attr_done = true;
    }

    const int TB = 256;

    // fork: weight-convert + GEMM1 (independent of edges) on s2; CSR chain on stream 0
    cudaEventRecord(g_ev_fork, 0);
    cudaStreamWaitEvent(g_s2, g_ev_fork, 0);
    {
        int tot = 128 * NFEATP + 64 * HID;
        k_cvtW<<<(tot + TB - 1) / TB, TB, 0, g_s2>>>(W1, W2);
        dim3 grid(1, (N_NODES + 127) / 128);
        k_gemm1_f16<<<grid, 256, G1_SMEM, g_s2>>>(x, p_h1h, N_NODES);
    }
    cudaEventRecord(g_ev_join, g_s2);

    // CSR + norms on default stream
    k_zero_deg<<<(N_NODES + TB - 1) / TB, TB>>>();
    k_count   <<<(N_EDGES + TB - 1) / TB, TB>>>(esrc, edst);
    int nb = (N_NODES + 1023) / 1024;
    k_scan_fused<<<nb, 1024>>>();
    k_fill      <<<(N_EDGES + TB - 1) / TB, TB>>>(esrc, edst);

    // join: agg1 needs h1h + csr + ns + nd
    cudaStreamWaitEvent(0, g_ev_join, 0);
    k_agg1<<<(N_NODES * 32 + TB - 1) / TB, TB>>>(b1);

    // layer 2
    {
        dim3 grid(1, (N_NODES + 127) / 128);
        k_gemm2_f16<<<grid, 256>>>(p_ns, p_h2h, N_NODES);
    }
    k_agg2<<<(N_NODES * 32 + TB - 1) / TB, TB>>>(b2, out);
}